// round 16
// baseline (speedup 1.0000x reference)
#include <cuda_runtime.h>
#include <math.h>

#define NCTA   128
#define NTHR   512
#define TSTEPS 1024
#define BATCH  64
#define HID    512
#define HB     (HID * BATCH)   // 32768
#define BT     (BATCH * TSTEPS)
#define BH     (BATCH * HID)

typedef unsigned long long u64;

// ---------------- global scratch (allocation-free) --------------------------
__device__ float    g_h0[2][HB];        // transposed: h[k*64 + b]
__device__ float    g_h1[2][HB];
__device__ float    g_yacc[2][BATCH];   // pre-relu y2 accumulators
__device__ unsigned g_flags[NCTA];      // per-CTA arrival generation
__device__ unsigned g_gen;              // broadcast generation

// ---------------- smem layout (float offsets) -------------------------------
// Weights k-major, un-duplicated: w[k][gate], gate-pairs feed f32x2 lanes.
// Reduction buffers now DISJOINT (we have SMEM headroom; removes the WAR
// syncthreads between Bh-reduce and Bi-store):
//   redT : Bh partials (alpha window) then A partials (gamma window)
//   redX : Bi partials (phase 2)
//   redC : C partials (phase 3)
#define OFF_WA    0          // Whh0: 512 x 12 = 6144
#define OFF_WBI   6144       // Wih1            = 6144
#define OFF_WBH   12288      // Whh1            = 6144
#define OFF_WC    18432      // Wo1: 512 x 4    = 2048
#define OFF_BASE  20480      // gi0 ctx part: 12x64 = 768
#define OFF_GSUMH 21248      // Bh sums + bias 12x64= 768
#define OFF_ARENA 22016      // redT 12288 | redX 12288 | redC 4096 = 28672
#define OFF_Y2    50688      // 256
#define OFF_MISC  50944      // wcolA12 bhhA12 biB12 bhB12 bC4 wo2_4 (pad 64)
#define SMEM_FLOATS 51008
#define SMEM_BYTES  (SMEM_FLOATS * 4)   // 204,032 B

__device__ __forceinline__ void fma2(u64 &d, u64 a, u64 b) {
    asm("fma.rn.f32x2 %0, %1, %2, %0;" : "+l"(d) : "l"(a), "l"(b));
}
__device__ __forceinline__ u64 dup(float x) {
    u64 r; asm("mov.b64 %0, {%1, %1};" : "=l"(r) : "f"(x)); return r;
}
__device__ __forceinline__ float2 unpack2(u64 v) {
    float2 r; asm("mov.b64 {%0, %1}, %2;" : "=f"(r.x), "=f"(r.y) : "l"(v));
    return r;
}
__device__ __forceinline__ float sigm(float x) { return 1.0f / (1.0f + __expf(-x)); }
__device__ __forceinline__ float tanh_f(float x) {
    return 2.0f / (1.0f + __expf(-2.0f * x)) - 1.0f;
}
__device__ __forceinline__ unsigned ldacq(const unsigned* p) {
    unsigned v;
    asm volatile("ld.acquire.gpu.u32 %0, [%1];" : "=r"(v) : "l"(p) : "memory");
    return v;
}
__device__ __forceinline__ void strel(unsigned* p, unsigned v) {
    asm volatile("st.release.gpu.u32 [%0], %1;" :: "l"(p), "r"(v) : "memory");
}

// Split grid barrier (two-hop, R6/R10-validated). Polling on threads 384..511.
__device__ __forceinline__ void bar_arrive(unsigned g) {
    __syncthreads();
    if (threadIdx.x == 0) strel(&g_flags[blockIdx.x], g);
}
__device__ __forceinline__ void bar_wait(unsigned g) {
    if (blockIdx.x == 0) {
        if (threadIdx.x >= 384) {
            while ((int)(ldacq(&g_flags[threadIdx.x - 384]) - g) < 0) { }
        }
        __syncthreads();
        if (threadIdx.x == 0) strel(&g_gen, g);
    } else {
        if (threadIdx.x == 384) {
            while ((int)(ldacq(&g_gen) - g) < 0) { }
        }
        __syncthreads();
    }
}

// 16-k FMA block: acc[2p+j] accumulates (gate 2p, gate 2p+1) for batch b0+j.
__device__ __forceinline__ void fma12(const float* __restrict__ wS, u64* acc,
                                      int kstart, const float2* v) {
    #pragma unroll
    for (int i = 0; i < 16; i++) {
        u64 va = dup(v[i].x), vb = dup(v[i].y);
        const ulonglong2* wp = (const ulonglong2*)(wS + (kstart + i) * 12);
        ulonglong2 w01 = wp[0], w23 = wp[1], w45 = wp[2];
        fma2(acc[0],  w01.x, va); fma2(acc[1],  w01.x, vb);
        fma2(acc[2],  w01.y, va); fma2(acc[3],  w01.y, vb);
        fma2(acc[4],  w23.x, va); fma2(acc[5],  w23.x, vb);
        fma2(acc[6],  w23.y, va); fma2(acc[7],  w23.y, vb);
        fma2(acc[8],  w45.x, va); fma2(acc[9],  w45.x, vb);
        fma2(acc[10], w45.y, va); fma2(acc[11], w45.y, vb);
    }
}
__device__ __forceinline__ void load16(const float* __restrict__ hp,
                                       float2* v, int kstart, int b0) {
    #pragma unroll
    for (int i = 0; i < 16; i++)
        v[i] = __ldcg((const float2*)(hp + (kstart + i) * 64 + b0));
}
__device__ __forceinline__ void store12(float* __restrict__ red, const u64* acc,
                                        int ks, int b0) {
    #pragma unroll
    for (int p = 0; p < 6; p++) {
        #pragma unroll
        for (int j = 0; j < 2; j++) {
            float2 f = unpack2(acc[2 * p + j]);
            red[((2 * p)     * 16 + ks) * 64 + b0 + j] = f.x;
            red[((2 * p + 1) * 16 + ks) * 64 + b0 + j] = f.y;
        }
    }
}

__global__ void __launch_bounds__(NTHR, 1)
decoder_rnn(const float* __restrict__ ctx,
            const float* __restrict__ Wih0, const float* __restrict__ Whh0,
            const float* __restrict__ bih0, const float* __restrict__ bhh0,
            const float* __restrict__ Wih1, const float* __restrict__ Whh1,
            const float* __restrict__ bih1, const float* __restrict__ bhh1,
            const float* __restrict__ Wo1,  const float* __restrict__ bo1,
            const float* __restrict__ Wo2,  const float* __restrict__ bo2p,
            float* __restrict__ out, int out_size)
{
    extern __shared__ float sm[];
    const int tid = threadIdx.x;
    const int cta = blockIdx.x;
    const int bp  = tid & 31;          // batch pair
    const int b0  = 2 * bp;
    const int ks  = tid >> 5;          // k-slice 0..15 (32 k each)
    const int kb  = ks * 32;
    const int be  = tid & 63;          // elementwise: batch (tid<256)
    const int re  = (tid >> 6) & 3;    // elementwise: local row 0..3
    const int jrow = cta * 4 + re;
    const int gR = re, gZ = 4 + re, gN = 8 + re;

    float* wA   = sm + OFF_WA;
    float* wBi  = sm + OFF_WBI;
    float* wBh  = sm + OFF_WBH;
    float* wC   = sm + OFF_WC;
    float* base = sm + OFF_BASE;
    float* gsumH = sm + OFF_GSUMH;
    float* redT = sm + OFF_ARENA;            // Bh (alpha) / A (gamma) partials
    float* redX = sm + OFF_ARENA + 12288;    // Bi partials (disjoint!)
    float* redC = sm + OFF_ARENA + 24576;    // C partials
    float* y2   = sm + OFF_Y2;
    float* wcolA = sm + OFF_MISC;      // 12
    float* bhhA  = wcolA + 12;         // 12
    float* biB   = bhhA + 12;          // 12
    float* bhB   = biB + 12;           // 12
    float* bC    = bhB + 12;           // 4
    float* wo2s  = bC + 4;             // 4

    // ---- prelude: weights -> SMEM, k-major [k][gate] -----------------------
    for (int idx = tid; idx < 12 * 512; idx += NTHR) {
        int g = idx / 512, k = idx & 511;
        int grow = (g >> 2) * 512 + cta * 4 + (g & 3);
        wA [k * 12 + g] = Whh0[grow * 512 + k];
        wBi[k * 12 + g] = Wih1[grow * 512 + k];
        wBh[k * 12 + g] = Whh1[grow * 512 + k];
    }
    for (int idx = tid; idx < 4 * 512; idx += NTHR) {
        int r = idx / 512, k = idx & 511;
        wC[k * 4 + r] = Wo1[(cta * 4 + r) * 512 + k];
    }
    if (tid < 12) {
        int grow = (tid >> 2) * 512 + cta * 4 + (tid & 3);
        wcolA[tid] = Wih0[grow * 513 + 512];   // Wih0 is (1536, 513): prev column
        bhhA[tid]  = bhh0[grow];
        biB[tid]   = bih1[grow];
        bhB[tid]   = bhh1[grow];
    }
    if (tid < 4) {
        bC[tid]   = bo1[cta * 4 + tid];
        wo2s[tid] = Wo2[cta * 4 + tid];
    }
    const float bo2 = bo2p[0];

    // gi0 ctx part (time-invariant): base[g*64+b] = Wih0[grow,:512].ctx[b]+bih0
    {
        int warp = tid >> 5, lane = tid & 31;
        for (int d = warp; d < 12 * 64; d += 16) {
            int g = d >> 6, b = d & 63;
            int grow = (g >> 2) * 512 + cta * 4 + (g & 3);
            const float* wr = Wih0 + (size_t)grow * 513;
            const float* cx = ctx + b * 512;
            float a = 0.0f;
            #pragma unroll 4
            for (int k = lane; k < 512; k += 32) a = fmaf(wr[k], cx[k], a);
            #pragma unroll
            for (int o = 16; o > 0; o >>= 1) a += __shfl_down_sync(0xffffffffu, a, o);
            if (lane == 0) base[g * 64 + b] = a + bih0[grow];
        }
    }

    // zero initial global state
    {
        int i = cta * NTHR + tid;
        if (i < HB) { g_h0[0][i] = 0.0f; g_h1[0][i] = 0.0f; }
        if (cta == 0 && tid < BATCH) { g_yacc[0][tid] = 0.0f; g_yacc[1][tid] = 0.0f; }
    }

    unsigned bg = ldacq(&g_gen);   // persistent across graph replays: relative
    bar_arrive(++bg);
    bar_wait(bg);

    // Carried A-GEMV sums (tid<256): initial A partials are zero -> bias only.
    float c_hr = 0, c_hz = 0, c_hn = 0, c_ir = 0, c_iz = 0, c_in = 0;
    float h0_own = 0.0f, h1_own = 0.0f;
    if (tid < 256) {
        c_hr = bhhA[gR]; c_hz = bhhA[gZ]; c_hn = bhhA[gN];
        c_ir = base[gR * 64 + be]; c_iz = base[gZ * 64 + be]; c_in = base[gN * 64 + be];
    }

    // ---- main recurrence ---------------------------------------------------
    for (int t = 0; t < TSTEPS; t++) {
        const int p = t & 1;

        // ===== phase 1: finish h0n from carried sums + y(t-1) ===============
        if (tid < 256) {
            float prev_y = 0.0f;
            if (t > 0) prev_y = fmaxf(__ldcg(&g_yacc[(t - 1) & 1][be]) + bo2, 0.0f);
            float r = sigm(c_ir + prev_y * wcolA[gR] + c_hr);
            float z = sigm(c_iz + prev_y * wcolA[gZ] + c_hz);
            float n = tanh_f(c_in + prev_y * wcolA[gN] + r * c_hn);
            float hn0 = (1.0f - z) * n + z * h0_own;
            h0_own = hn0;
            g_h0[1 - p][jrow * 64 + be] = hn0;
            if (cta == 0 && t > 0 && re == 0) out[be * TSTEPS + (t - 1)] = prev_y;
        }
        // Bh preloads (old h1, warm) BEFORE arrive: hide under barrier/phase1.
        const float* hp1 = g_h1[p];
        float2 vh[16], vh2[16];
        load16(hp1, vh,  kb,      b0);
        load16(hp1, vh2, kb + 16, b0);
        bar_arrive(++bg);                        // alpha: h0n published

        {   // Bh = Whh1 . h1(t), fully inside the alpha window
            u64 acc[12];
            #pragma unroll
            for (int g = 0; g < 12; g++) acc[g] = 0ull;
            fma12(wBh, acc, kb, vh);
            fma12(wBh, acc, kb + 16, vh2);
            store12(redT, acc, ks, b0);
        }
        bar_wait(bg);                            // alpha (before Bh reduce)
        if (cta == 1 && tid < BATCH) __stcg(&g_yacc[(t + 1) & 1][tid], 0.0f);

        // Issue Bi preload (fresh h0n) immediately; its ramp hides under the
        // Bh reduce below. redT/redX disjoint -> no syncthreads needed between
        // Bh-reduce (reads redT) and Bi fma/store (writes redX): warps overlap.
        const float* xp = g_h0[1 - p];           // h0n(t) = h0(t+1)
        float2 vx[32];
        #pragma unroll
        for (int i = 0; i < 32; i++)
            vx[i] = __ldcg((const float2*)(xp + (kb + i) * 64 + b0));
        if (tid < 256) {
            float sr = bhB[gR], sz = bhB[gZ], sn = bhB[gN];
            #pragma unroll
            for (int sl = 0; sl < 16; sl++) {
                sr += redT[(gR * 16 + sl) * 64 + be];
                sz += redT[(gZ * 16 + sl) * 64 + be];
                sn += redT[(gN * 16 + sl) * 64 + be];
            }
            gsumH[gR * 64 + be] = sr;
            gsumH[gZ * 64 + be] = sz;
            gsumH[gN * 64 + be] = sn;
        }

        // ===== phase 2: Bi + h1n (no barrier before: disjoint buffers) ======
        {
            u64 acc[12];
            #pragma unroll
            for (int g = 0; g < 12; g++) acc[g] = 0ull;
            fma12(wBi, acc, kb, vx);
            fma12(wBi, acc, kb + 16, vx + 16);
            store12(redX, acc, ks, b0);
        }
        __syncthreads();
        if (tid < 256) {
            float ir = biB[gR], iz = biB[gZ], in_ = biB[gN];
            #pragma unroll
            for (int sl = 0; sl < 16; sl++) {
                ir  += redX[(gR * 16 + sl) * 64 + be];
                iz  += redX[(gZ * 16 + sl) * 64 + be];
                in_ += redX[(gN * 16 + sl) * 64 + be];
            }
            float r = sigm(ir + gsumH[gR * 64 + be]);
            float z = sigm(iz + gsumH[gZ * 64 + be]);
            float n = tanh_f(in_ + r * gsumH[gN * 64 + be]);
            float hn1 = (1.0f - z) * n + z * h1_own;
            h1_own = hn1;
            g_h1[1 - p][jrow * 64 + be] = hn1;
        }
        bar_arrive(++bg);                        // beta: h1n published

        // A = Whh0 . h0n: half1 fma in beta window; half2 activations preloaded
        u64 accA[12];
        #pragma unroll
        for (int g = 0; g < 12; g++) accA[g] = 0ull;
        float2 vA1[16], vA2[16];
        load16(xp, vA1, kb, b0);                 // warm (just read by Bi)
        load16(xp, vA2, kb + 16, b0);
        fma12(wA, accA, kb, vA1);
        bar_wait(bg);                            // beta

        // ===== phase 3: C = Wo1 . h1n; ramps hidden under A-half2 fma =======
        {
            const float* yp = g_h1[1 - p];
            float2 vy1[16];
            load16(yp, vy1, kb, b0);             // fresh h1n: ramp starts
            fma12(wA, accA, kb + 16, vA2);       // A half2 fma hides vy1 ramp
            float2 vy2[16];
            load16(yp, vy2, kb + 16, b0);        // ramp hidden under C fma(vy1)
            u64 accC[4];
            #pragma unroll
            for (int r = 0; r < 4; r++) accC[r] = 0ull;
            #pragma unroll
            for (int i = 0; i < 16; i++) {
                u64 va = dup(vy1[i].x), vb = dup(vy1[i].y);
                ulonglong2 w = *(const ulonglong2*)(wC + (kb + i) * 4);
                fma2(accC[0], w.x, va); fma2(accC[1], w.x, vb);
                fma2(accC[2], w.y, va); fma2(accC[3], w.y, vb);
            }
            #pragma unroll
            for (int i = 0; i < 16; i++) {
                u64 va = dup(vy2[i].x), vb = dup(vy2[i].y);
                ulonglong2 w = *(const ulonglong2*)(wC + (kb + 16 + i) * 4);
                fma2(accC[0], w.x, va); fma2(accC[1], w.x, vb);
                fma2(accC[2], w.y, va); fma2(accC[3], w.y, vb);
            }
            #pragma unroll
            for (int pr = 0; pr < 2; pr++) {
                #pragma unroll
                for (int j = 0; j < 2; j++) {
                    float2 f = unpack2(accC[2 * pr + j]);
                    redC[((2 * pr)     * 16 + ks) * 64 + b0 + j] = f.x;
                    redC[((2 * pr + 1) * 16 + ks) * 64 + b0 + j] = f.y;
                }
            }
        }
        __syncthreads();
        if (tid < 256) {
            float s = bC[re];
            #pragma unroll
            for (int sl = 0; sl < 16; sl++) s += redC[(re * 16 + sl) * 64 + be];
            y2[re * 64 + be] = fmaxf(s, 0.0f) * wo2s[re];
        }
        __syncthreads();
        if (tid < 64) {
            float v = y2[tid] + y2[64 + tid] + y2[128 + tid] + y2[192 + tid];
            atomicAdd(&g_yacc[t & 1][tid], v);
        }
        bar_arrive(++bg);                        // gamma: y published

        // gamma window: A partial store (redT, free now) + CTA-local reduction
        store12(redT, accA, ks, b0);
        __syncthreads();
        if (tid < 256) {
            float hr = bhhA[gR], hz = bhhA[gZ], hn = bhhA[gN];
            #pragma unroll
            for (int sl = 0; sl < 16; sl++) {
                hr += redT[(gR * 16 + sl) * 64 + be];
                hz += redT[(gZ * 16 + sl) * 64 + be];
                hn += redT[(gN * 16 + sl) * 64 + be];
            }
            c_hr = hr; c_hz = hz; c_hn = hn;
            c_ir = base[gR * 64 + be];
            c_iz = base[gZ * 64 + be];
            c_in = base[gN * 64 + be];
        }
        bar_wait(bg);                            // gamma
    }

    // ---- epilogue ----------------------------------------------------------
    if (cta == 0 && tid < BATCH)
        out[tid * TSTEPS + (TSTEPS - 1)] = fmaxf(__ldcg(&g_yacc[1][tid]) + bo2, 0.0f);
    if (out_size >= BT + 2 * BH && tid < 256) {
        out[BT + be * HID + jrow]      = h0_own;
        out[BT + BH + be * HID + jrow] = h1_own;
    }
}

extern "C" void kernel_launch(void* const* d_in, const int* in_sizes, int n_in,
                              void* d_out, int out_size) {
    (void)in_sizes; (void)n_in;
    cudaFuncSetAttribute(decoder_rnn, cudaFuncAttributeMaxDynamicSharedMemorySize,
                         SMEM_BYTES);
    decoder_rnn<<<NCTA, NTHR, SMEM_BYTES>>>(
        (const float*)d_in[0],                           // context_vector
        (const float*)d_in[2],  (const float*)d_in[3],   // W_ih0, W_hh0
        (const float*)d_in[4],  (const float*)d_in[5],   // b_ih0, b_hh0
        (const float*)d_in[6],  (const float*)d_in[7],   // W_ih1, W_hh1
        (const float*)d_in[8],  (const float*)d_in[9],   // b_ih1, b_hh1
        (const float*)d_in[10], (const float*)d_in[11],  // W_o1, b_o1
        (const float*)d_in[12], (const float*)d_in[13],  // W_o2, b_o2
        (float*)d_out, out_size);
}

// round 17
// speedup vs baseline: 1.0666x; 1.0666x over previous
#include <cuda_runtime.h>
#include <math.h>

#define NCTA   128
#define NTHR   512
#define TSTEPS 1024
#define BATCH  64
#define HID    512
#define HB     (HID * BATCH)   // 32768
#define BT     (BATCH * TSTEPS)
#define BH     (BATCH * HID)

typedef unsigned long long u64;

// ---------------- global scratch (allocation-free) --------------------------
__device__ float    g_h0[2][HB];        // transposed: h[k*64 + b]
__device__ float    g_h1[2][HB];
__device__ float    g_yacc[2][BATCH];   // pre-relu y2 accumulators
__device__ unsigned g_flags[NCTA];      // per-CTA arrival generation
__device__ unsigned g_gen;              // broadcast generation

// ---------------- smem layout (float offsets) -------------------------------
// Weights k-major, un-duplicated: w[k][gate], gate-pairs feed f32x2 lanes.
// Arena overlap (timeline-safe, R10/R13-validated):
//   redA = arena[0..12288)      : Whh0 . h0(t+1) partials (gamma window only)
//   redT = arena[4096..16384)   : Bh / Bi transient partials
//   redC = arena[12288..16384)  : C transient partials
#define OFF_WA    0          // Whh0: 512 x 12 = 6144
#define OFF_WBI   6144       // Wih1            = 6144
#define OFF_WBH   12288      // Whh1            = 6144
#define OFF_WC    18432      // Wo1: 512 x 4    = 2048
#define OFF_BASE  20480      // gi0 ctx part: 12x64 = 768
#define OFF_GSUMH 21248      // Bh sums + bias 12x64= 768
#define OFF_ARENA 22016      // 16384
#define OFF_Y2    38400      // 256
#define OFF_MISC  38656      // wcolA12 bhhA12 biB12 bhB12 bC4 wo2_4 = 56
#define SMEM_FLOATS 38712
#define SMEM_BYTES  (SMEM_FLOATS * 4)   // 154,848 B

__device__ __forceinline__ void fma2(u64 &d, u64 a, u64 b) {
    asm("fma.rn.f32x2 %0, %1, %2, %0;" : "+l"(d) : "l"(a), "l"(b));
}
__device__ __forceinline__ u64 dup(float x) {
    u64 r; asm("mov.b64 %0, {%1, %1};" : "=l"(r) : "f"(x)); return r;
}
__device__ __forceinline__ float2 unpack2(u64 v) {
    float2 r; asm("mov.b64 {%0, %1}, %2;" : "=f"(r.x), "=f"(r.y) : "l"(v));
    return r;
}
__device__ __forceinline__ float sigm(float x) { return 1.0f / (1.0f + __expf(-x)); }
__device__ __forceinline__ float tanh_f(float x) {
    return 2.0f / (1.0f + __expf(-2.0f * x)) - 1.0f;
}
__device__ __forceinline__ unsigned ldacq(const unsigned* p) {
    unsigned v;
    asm volatile("ld.acquire.gpu.u32 %0, [%1];" : "=r"(v) : "l"(p) : "memory");
    return v;
}
__device__ __forceinline__ void strel(unsigned* p, unsigned v) {
    asm volatile("st.release.gpu.u32 [%0], %1;" :: "l"(p), "r"(v) : "memory");
}

// Split grid barrier (two-hop, R6/R10-validated). Polling on threads 384..511.
__device__ __forceinline__ void bar_arrive(unsigned g) {
    __syncthreads();
    if (threadIdx.x == 0) strel(&g_flags[blockIdx.x], g);
}
__device__ __forceinline__ void bar_wait(unsigned g) {
    if (blockIdx.x == 0) {
        if (threadIdx.x >= 384) {
            while ((int)(ldacq(&g_flags[threadIdx.x - 384]) - g) < 0) { }
        }
        __syncthreads();
        if (threadIdx.x == 0) strel(&g_gen, g);
    } else {
        if (threadIdx.x == 384) {
            while ((int)(ldacq(&g_gen) - g) < 0) { }
        }
        __syncthreads();
    }
}

// 16-k FMA block: acc[2p+j] accumulates (gate 2p, gate 2p+1) for batch b0+j.
__device__ __forceinline__ void fma12(const float* __restrict__ wS, u64* acc,
                                      int kstart, const float2* v) {
    #pragma unroll
    for (int i = 0; i < 16; i++) {
        u64 va = dup(v[i].x), vb = dup(v[i].y);
        const ulonglong2* wp = (const ulonglong2*)(wS + (kstart + i) * 12);
        ulonglong2 w01 = wp[0], w23 = wp[1], w45 = wp[2];
        fma2(acc[0],  w01.x, va); fma2(acc[1],  w01.x, vb);
        fma2(acc[2],  w01.y, va); fma2(acc[3],  w01.y, vb);
        fma2(acc[4],  w23.x, va); fma2(acc[5],  w23.x, vb);
        fma2(acc[6],  w23.y, va); fma2(acc[7],  w23.y, vb);
        fma2(acc[8],  w45.x, va); fma2(acc[9],  w45.x, vb);
        fma2(acc[10], w45.y, va); fma2(acc[11], w45.y, vb);
    }
}
__device__ __forceinline__ void load16(const float* __restrict__ hp,
                                       float2* v, int kstart, int b0) {
    #pragma unroll
    for (int i = 0; i < 16; i++)
        v[i] = __ldcg((const float2*)(hp + (kstart + i) * 64 + b0));
}
__device__ __forceinline__ void store12(float* __restrict__ red, const u64* acc,
                                        int ks, int b0) {
    #pragma unroll
    for (int p = 0; p < 6; p++) {
        #pragma unroll
        for (int j = 0; j < 2; j++) {
            float2 f = unpack2(acc[2 * p + j]);
            red[((2 * p)     * 16 + ks) * 64 + b0 + j] = f.x;
            red[((2 * p + 1) * 16 + ks) * 64 + b0 + j] = f.y;
        }
    }
}

__global__ void __launch_bounds__(NTHR, 1)
decoder_rnn(const float* __restrict__ ctx,
            const float* __restrict__ Wih0, const float* __restrict__ Whh0,
            const float* __restrict__ bih0, const float* __restrict__ bhh0,
            const float* __restrict__ Wih1, const float* __restrict__ Whh1,
            const float* __restrict__ bih1, const float* __restrict__ bhh1,
            const float* __restrict__ Wo1,  const float* __restrict__ bo1,
            const float* __restrict__ Wo2,  const float* __restrict__ bo2p,
            float* __restrict__ out, int out_size)
{
    extern __shared__ float sm[];
    const int tid = threadIdx.x;
    const int cta = blockIdx.x;
    const int bp  = tid & 31;          // batch pair
    const int b0  = 2 * bp;
    const int ks  = tid >> 5;          // k-slice 0..15 (32 k each)
    const int kb  = ks * 32;
    const int be  = tid & 63;          // elementwise: batch (tid<256)
    const int re  = (tid >> 6) & 3;    // elementwise: local row 0..3
    const int jrow = cta * 4 + re;
    const int gR = re, gZ = 4 + re, gN = 8 + re;

    float* wA   = sm + OFF_WA;
    float* wBi  = sm + OFF_WBI;
    float* wBh  = sm + OFF_WBH;
    float* wC   = sm + OFF_WC;
    float* base = sm + OFF_BASE;
    float* gsumH = sm + OFF_GSUMH;
    float* redA = sm + OFF_ARENA;           // gamma-window-local partials
    float* redT = sm + OFF_ARENA + 4096;    // transient Bh/Bi
    float* redC = sm + OFF_ARENA + 12288;   // transient C
    float* y2   = sm + OFF_Y2;
    float* wcolA = sm + OFF_MISC;      // 12
    float* bhhA  = wcolA + 12;         // 12
    float* biB   = bhhA + 12;          // 12
    float* bhB   = biB + 12;           // 12
    float* bC    = bhB + 12;           // 4
    float* wo2s  = bC + 4;             // 4

    // ---- prelude: weights -> SMEM, k-major [k][gate] -----------------------
    for (int idx = tid; idx < 12 * 512; idx += NTHR) {
        int g = idx / 512, k = idx & 511;
        int grow = (g >> 2) * 512 + cta * 4 + (g & 3);
        wA [k * 12 + g] = Whh0[grow * 512 + k];
        wBi[k * 12 + g] = Wih1[grow * 512 + k];
        wBh[k * 12 + g] = Whh1[grow * 512 + k];
    }
    for (int idx = tid; idx < 4 * 512; idx += NTHR) {
        int r = idx / 512, k = idx & 511;
        wC[k * 4 + r] = Wo1[(cta * 4 + r) * 512 + k];
    }
    if (tid < 12) {
        int grow = (tid >> 2) * 512 + cta * 4 + (tid & 3);
        wcolA[tid] = Wih0[grow * 513 + 512];   // Wih0 is (1536, 513): prev column
        bhhA[tid]  = bhh0[grow];
        biB[tid]   = bih1[grow];
        bhB[tid]   = bhh1[grow];
    }
    if (tid < 4) {
        bC[tid]   = bo1[cta * 4 + tid];
        wo2s[tid] = Wo2[cta * 4 + tid];
    }
    const float bo2 = bo2p[0];

    // gi0 ctx part (time-invariant): base[g*64+b] = Wih0[grow,:512].ctx[b]+bih0
    {
        int warp = tid >> 5, lane = tid & 31;
        for (int d = warp; d < 12 * 64; d += 16) {
            int g = d >> 6, b = d & 63;
            int grow = (g >> 2) * 512 + cta * 4 + (g & 3);
            const float* wr = Wih0 + (size_t)grow * 513;
            const float* cx = ctx + b * 512;
            float a = 0.0f;
            #pragma unroll 4
            for (int k = lane; k < 512; k += 32) a = fmaf(wr[k], cx[k], a);
            #pragma unroll
            for (int o = 16; o > 0; o >>= 1) a += __shfl_down_sync(0xffffffffu, a, o);
            if (lane == 0) base[g * 64 + b] = a + bih0[grow];
        }
    }

    // zero initial global state
    {
        int i = cta * NTHR + tid;
        if (i < HB) { g_h0[0][i] = 0.0f; g_h1[0][i] = 0.0f; }
        if (cta == 0 && tid < BATCH) { g_yacc[0][tid] = 0.0f; g_yacc[1][tid] = 0.0f; }
    }

    unsigned bg = ldacq(&g_gen);   // persistent across graph replays: relative
    bar_arrive(++bg);
    bar_wait(bg);

    // Carried A-GEMV sums (tid<256): initial redA is zero -> bias only.
    float c_hr = 0, c_hz = 0, c_hn = 0, c_ir = 0, c_iz = 0, c_in = 0;
    float h0_own = 0.0f, h1_own = 0.0f;
    if (tid < 256) {
        c_hr = bhhA[gR]; c_hz = bhhA[gZ]; c_hn = bhhA[gN];
        c_ir = base[gR * 64 + be]; c_iz = base[gZ * 64 + be]; c_in = base[gN * 64 + be];
    }

    // Bh preloads carried across the loop boundary: for step t they hold
    // h1(t) = g_h1[t&1]. Initial load (t=0) reads the zeroed buffer 0.
    float2 vh[16], vh2[16];
    load16(g_h1[0], vh,  kb,      b0);
    load16(g_h1[0], vh2, kb + 16, b0);

    // ---- main recurrence ---------------------------------------------------
    for (int t = 0; t < TSTEPS; t++) {
        const int p = t & 1;

        // ===== phase 1: finish h0n from carried sums + y(t-1) ===============
        if (tid < 256) {
            float prev_y = 0.0f;
            if (t > 0) prev_y = fmaxf(__ldcg(&g_yacc[(t - 1) & 1][be]) + bo2, 0.0f);
            float r = sigm(c_ir + prev_y * wcolA[gR] + c_hr);
            float z = sigm(c_iz + prev_y * wcolA[gZ] + c_hz);
            float n = tanh_f(c_in + prev_y * wcolA[gN] + r * c_hn);
            float hn0 = (1.0f - z) * n + z * h0_own;
            h0_own = hn0;
            g_h0[1 - p][jrow * 64 + be] = hn0;
            if (cta == 0 && t > 0 && re == 0) out[be * TSTEPS + (t - 1)] = prev_y;
        }
        bar_arrive(++bg);                        // alpha: h0n published

        {   // Bh = Whh1 . h1(t), vh/vh2 preloaded in previous gamma window
            u64 acc[12];
            #pragma unroll
            for (int g = 0; g < 12; g++) acc[g] = 0ull;
            fma12(wBh, acc, kb, vh);
            fma12(wBh, acc, kb + 16, vh2);
            store12(redT, acc, ks, b0);
        }
        bar_wait(bg);                            // alpha (before Bh reduce)
        if (cta == 1 && tid < BATCH) __stcg(&g_yacc[(t + 1) & 1][tid], 0.0f);

        // Issue Bi preload (fresh h0n) immediately; its ramp hides under the
        // Bh reduce below. redT stores are ordered by bar_wait's syncthreads.
        const float* xp = g_h0[1 - p];           // h0n(t) = h0(t+1)
        float2 vx[32];
        #pragma unroll
        for (int i = 0; i < 32; i++)
            vx[i] = __ldcg((const float2*)(xp + (kb + i) * 64 + b0));
        if (tid < 256) {
            float sr = bhB[gR], sz = bhB[gZ], sn = bhB[gN];
            #pragma unroll
            for (int sl = 0; sl < 16; sl++) {
                sr += redT[(gR * 16 + sl) * 64 + be];
                sz += redT[(gZ * 16 + sl) * 64 + be];
                sn += redT[(gN * 16 + sl) * 64 + be];
            }
            gsumH[gR * 64 + be] = sr;
            gsumH[gZ * 64 + be] = sz;
            gsumH[gN * 64 + be] = sn;
        }
        __syncthreads();                         // redT readers done before Bi store

        // ===== phase 2: Bi + h1n =====
        {
            u64 acc[12];
            #pragma unroll
            for (int g = 0; g < 12; g++) acc[g] = 0ull;
            fma12(wBi, acc, kb, vx);
            fma12(wBi, acc, kb + 16, vx + 16);
            store12(redT, acc, ks, b0);
        }
        __syncthreads();
        if (tid < 256) {
            float ir = biB[gR], iz = biB[gZ], in_ = biB[gN];
            #pragma unroll
            for (int sl = 0; sl < 16; sl++) {
                ir  += redT[(gR * 16 + sl) * 64 + be];
                iz  += redT[(gZ * 16 + sl) * 64 + be];
                in_ += redT[(gN * 16 + sl) * 64 + be];
            }
            float r = sigm(ir + gsumH[gR * 64 + be]);
            float z = sigm(iz + gsumH[gZ * 64 + be]);
            float n = tanh_f(in_ + r * gsumH[gN * 64 + be]);
            float hn1 = (1.0f - z) * n + z * h1_own;
            h1_own = hn1;
            g_h1[1 - p][jrow * 64 + be] = hn1;
        }
        bar_arrive(++bg);                        // beta: h1n published

        // A = Whh0 . h0n: half1 fma in beta window; half2 activations preloaded
        u64 accA[12];
        #pragma unroll
        for (int g = 0; g < 12; g++) accA[g] = 0ull;
        float2 vA1[16], vA2[16];
        load16(xp, vA1, kb, b0);                 // warm (just read by Bi)
        load16(xp, vA2, kb + 16, b0);
        fma12(wA, accA, kb, vA1);
        bar_wait(bg);                            // beta

        // ===== phase 3: C = Wo1 . h1n; ramps hidden under A-half2 fma =======
        {
            const float* yp = g_h1[1 - p];
            float2 vy1[16];
            load16(yp, vy1, kb, b0);             // fresh h1n: ramp starts
            fma12(wA, accA, kb + 16, vA2);       // A half2 fma hides vy1 ramp
            float2 vy2[16];
            load16(yp, vy2, kb + 16, b0);        // ramp hidden under C fma(vy1)
            u64 accC[4];
            #pragma unroll
            for (int r = 0; r < 4; r++) accC[r] = 0ull;
            #pragma unroll
            for (int i = 0; i < 16; i++) {
                u64 va = dup(vy1[i].x), vb = dup(vy1[i].y);
                ulonglong2 w = *(const ulonglong2*)(wC + (kb + i) * 4);
                fma2(accC[0], w.x, va); fma2(accC[1], w.x, vb);
                fma2(accC[2], w.y, va); fma2(accC[3], w.y, vb);
            }
            #pragma unroll
            for (int i = 0; i < 16; i++) {
                u64 va = dup(vy2[i].x), vb = dup(vy2[i].y);
                ulonglong2 w = *(const ulonglong2*)(wC + (kb + 16 + i) * 4);
                fma2(accC[0], w.x, va); fma2(accC[1], w.x, vb);
                fma2(accC[2], w.y, va); fma2(accC[3], w.y, vb);
            }
            #pragma unroll
            for (int pr = 0; pr < 2; pr++) {
                #pragma unroll
                for (int j = 0; j < 2; j++) {
                    float2 f = unpack2(accC[2 * pr + j]);
                    redC[((2 * pr)     * 16 + ks) * 64 + b0 + j] = f.x;
                    redC[((2 * pr + 1) * 16 + ks) * 64 + b0 + j] = f.y;
                }
            }
        }
        __syncthreads();
        if (tid < 256) {
            float s = bC[re];
            #pragma unroll
            for (int sl = 0; sl < 16; sl++) s += redC[(re * 16 + sl) * 64 + be];
            y2[re * 64 + be] = fmaxf(s, 0.0f) * wo2s[re];
        }
        __syncthreads();
        if (tid < 64) {
            float v = y2[tid] + y2[64 + tid] + y2[128 + tid] + y2[192 + tid];
            atomicAdd(&g_yacc[t & 1][tid], v);
        }
        bar_arrive(++bg);                        // gamma: y published

        // gamma window: A partial store + NEXT step's Bh preload (h1(t+1) =
        // g_h1[1-p], published at beta(t) and already waited on) + A reduce.
        store12(redA, accA, ks, b0);
        {
            const float* hp1n = g_h1[1 - p];
            load16(hp1n, vh,  kb,      b0);
            load16(hp1n, vh2, kb + 16, b0);
        }
        __syncthreads();
        if (tid < 256) {
            float hr = bhhA[gR], hz = bhhA[gZ], hn = bhhA[gN];
            #pragma unroll
            for (int sl = 0; sl < 16; sl++) {
                hr += redA[(gR * 16 + sl) * 64 + be];
                hz += redA[(gZ * 16 + sl) * 64 + be];
                hn += redA[(gN * 16 + sl) * 64 + be];
            }
            c_hr = hr; c_hz = hz; c_hn = hn;
            c_ir = base[gR * 64 + be];
            c_iz = base[gZ * 64 + be];
            c_in = base[gN * 64 + be];
        }
        bar_wait(bg);                            // gamma
    }

    // ---- epilogue ----------------------------------------------------------
    if (cta == 0 && tid < BATCH)
        out[tid * TSTEPS + (TSTEPS - 1)] = fmaxf(__ldcg(&g_yacc[1][tid]) + bo2, 0.0f);
    if (out_size >= BT + 2 * BH && tid < 256) {
        out[BT + be * HID + jrow]      = h0_own;
        out[BT + BH + be * HID + jrow] = h1_own;
    }
}

extern "C" void kernel_launch(void* const* d_in, const int* in_sizes, int n_in,
                              void* d_out, int out_size) {
    (void)in_sizes; (void)n_in;
    cudaFuncSetAttribute(decoder_rnn, cudaFuncAttributeMaxDynamicSharedMemorySize,
                         SMEM_BYTES);
    decoder_rnn<<<NCTA, NTHR, SMEM_BYTES>>>(
        (const float*)d_in[0],                           // context_vector
        (const float*)d_in[2],  (const float*)d_in[3],   // W_ih0, W_hh0
        (const float*)d_in[4],  (const float*)d_in[5],   // b_ih0, b_hh0
        (const float*)d_in[6],  (const float*)d_in[7],   // W_ih1, W_hh1
        (const float*)d_in[8],  (const float*)d_in[9],   // b_ih1, b_hh1
        (const float*)d_in[10], (const float*)d_in[11],  // W_o1, b_o1
        (const float*)d_in[12], (const float*)d_in[13],  // W_o2, b_o2
        (float*)d_out, out_size);
}